// round 1
// baseline (speedup 1.0000x reference)
#include <cuda_runtime.h>
#include <math.h>

// Problem constants
#define BB 8
#define TT 4096
#define DD 1024
#define RR 512
#define N2R 1024          // 2R
#define MM (BB*TT)        // 32768 rows
#define NN 1536           // R + 2R output cols of fused GEMM
#define KK 1024           // D
#define LCH 64            // chunk length for scan
#define CCH 64            // chunks = T / LCH

// Scratch (device globals; no allocation allowed in kernel_launch)
__device__ float g_x [MM * RR];            // 64 MB : u @ W_proj^T
__device__ float g_ar[RR], g_ai[RR];
__device__ float g_aLr[RR], g_aLi[RR];
__device__ float g_Pr[BB*CCH*RR], g_Pi[BB*CCH*RR];  // chunk local sums
__device__ float g_Sr[BB*CCH*RR], g_Si[BB*CCH*RR];  // chunk start states

// ---------------------------------------------------------------------------
// Setup: per-channel recurrence coefficients a and a^L
// ---------------------------------------------------------------------------
__global__ void setup_k(const float* __restrict__ lambda_raw,
                        const float* __restrict__ omega) {
    int r = threadIdx.x;
    float lr  = lambda_raw[r];
    float sig = 1.0f / (1.0f + expf(-lr));
    float lam = -5.0f * sig;
    float mag = expf(lam);
    float w   = omega[r];
    float sw, cw;
    sincosf(w, &sw, &cw);
    g_ar[r] = mag * cw;
    g_ai[r] = mag * sw;
    float magL = expf(lam * (float)LCH);   // ~exp(-160) -> 0, fine
    float sl, cl;
    sincosf(w * (float)LCH, &sl, &cl);
    g_aLr[r] = magL * cl;
    g_aLi[r] = magL * sl;
}

// ---------------------------------------------------------------------------
// Fused GEMM: C[m,n] = sum_k u[m,k] * Wcat[n,k]
//   n in [0,512)    -> W_proj row n      -> g_x[m*512 + n]
//   n in [512,1536) -> W_res row n-512   -> out[m*1024 + (n-512)]  (residual)
// 128x128 tile, BK=16, 8x8 per thread, register-prefetched loads.
// ---------------------------------------------------------------------------
#define BM 128
#define BN 128
#define BK 16

__global__ void __launch_bounds__(256) gemm_k(const float* __restrict__ u,
                                              const float* __restrict__ Wp,
                                              const float* __restrict__ Wr,
                                              float* __restrict__ outRes) {
    __shared__ float As[BK][BM];
    __shared__ float Bs[BK][BN];

    const int bx = blockIdx.x;   // n-tile 0..11
    const int by = blockIdx.y;   // m-tile 0..255
    const int tid = threadIdx.x;

    const float* Wsrc;
    float* Cbase;
    int Cld;
    if (bx < 4) {
        Wsrc  = Wp + (size_t)bx * BN * KK;
        Cbase = g_x + (size_t)by * BM * RR + bx * BN;
        Cld   = RR;
    } else {
        Wsrc  = Wr + (size_t)(bx * BN - 512) * KK;
        Cbase = outRes + (size_t)by * BM * N2R + (bx * BN - 512);
        Cld   = N2R;
    }
    const float* Au = u + (size_t)by * BM * KK;

    const int ldRow = tid >> 1;        // 0..127 : row of A tile / row(n) of B tile
    const int ldC4  = (tid & 1);       // float4 column group base (0 or 1; +2 for 2nd)

    const int ty = tid >> 4;           // 0..15
    const int tx = tid & 15;           // 0..15

    float acc[8][8];
    #pragma unroll
    for (int i = 0; i < 8; i++)
        #pragma unroll
        for (int j = 0; j < 8; j++) acc[i][j] = 0.0f;

    float4 pa[2], pb[2];
    // preload tile 0
    #pragma unroll
    for (int l = 0; l < 2; l++) {
        int c0 = (ldC4 + 2 * l) * 4;
        pa[l] = *(const float4*)(Au   + (size_t)ldRow * KK + c0);
        pb[l] = *(const float4*)(Wsrc + (size_t)ldRow * KK + c0);
    }

    for (int kt = 0; kt < KK; kt += BK) {
        // stage prefetched registers into shared (transposed)
        #pragma unroll
        for (int l = 0; l < 2; l++) {
            int c0 = (ldC4 + 2 * l) * 4;
            As[c0 + 0][ldRow] = pa[l].x;
            As[c0 + 1][ldRow] = pa[l].y;
            As[c0 + 2][ldRow] = pa[l].z;
            As[c0 + 3][ldRow] = pa[l].w;
            Bs[c0 + 0][ldRow] = pb[l].x;
            Bs[c0 + 1][ldRow] = pb[l].y;
            Bs[c0 + 2][ldRow] = pb[l].z;
            Bs[c0 + 3][ldRow] = pb[l].w;
        }
        __syncthreads();

        // issue next tile's global loads early (hidden under compute)
        if (kt + BK < KK) {
            #pragma unroll
            for (int l = 0; l < 2; l++) {
                int c0 = (ldC4 + 2 * l) * 4;
                pa[l] = *(const float4*)(Au   + (size_t)ldRow * KK + kt + BK + c0);
                pb[l] = *(const float4*)(Wsrc + (size_t)ldRow * KK + kt + BK + c0);
            }
        }

        #pragma unroll
        for (int k = 0; k < BK; k++) {
            float ra[8], rb[8];
            *(float4*)(ra)     = *(const float4*)(&As[k][ty * 8]);
            *(float4*)(ra + 4) = *(const float4*)(&As[k][ty * 8 + 4]);
            *(float4*)(rb)     = *(const float4*)(&Bs[k][tx * 8]);
            *(float4*)(rb + 4) = *(const float4*)(&Bs[k][tx * 8 + 4]);
            #pragma unroll
            for (int i = 0; i < 8; i++)
                #pragma unroll
                for (int j = 0; j < 8; j++)
                    acc[i][j] = fmaf(ra[i], rb[j], acc[i][j]);
        }
        __syncthreads();
    }

    #pragma unroll
    for (int i = 0; i < 8; i++) {
        float* cp = Cbase + (size_t)(ty * 8 + i) * Cld + tx * 8;
        *(float4*)(cp)     = make_float4(acc[i][0], acc[i][1], acc[i][2], acc[i][3]);
        *(float4*)(cp + 4) = make_float4(acc[i][4], acc[i][5], acc[i][6], acc[i][7]);
    }
}

// ---------------------------------------------------------------------------
// Scan phase 1: per (b, chunk, r) local recurrence with zero init -> P
// ---------------------------------------------------------------------------
__global__ void __launch_bounds__(512) scan1_k() {
    const int r = threadIdx.x;
    const int c = blockIdx.x;
    const int b = blockIdx.y;
    const float ar = g_ar[r], ai = g_ai[r];
    const float* xp = g_x + ((size_t)(b * TT + c * LCH)) * RR + r;
    float hr = 0.0f, hi = 0.0f;
    #pragma unroll 4
    for (int j = 0; j < LCH; j++) {
        float x = xp[(size_t)j * RR];
        float nhr = fmaf(ar, hr, fmaf(-ai, hi, x));
        float nhi = fmaf(ar, hi, ai * hr);
        hr = nhr; hi = nhi;
    }
    int idx = (b * CCH + c) * RR + r;
    g_Pr[idx] = hr;
    g_Pi[idx] = hi;
}

// ---------------------------------------------------------------------------
// Scan phase 2: sequential combine across chunks -> chunk start states S,
// plus final state outputs (final_r, final_i) appended after `out`.
// ---------------------------------------------------------------------------
__global__ void __launch_bounds__(512) scan2_k(const float* __restrict__ h0r,
                                               const float* __restrict__ h0i,
                                               float* __restrict__ out,
                                               int out_size) {
    const int r = threadIdx.x;
    const int b = blockIdx.x;
    const float aLr = g_aLr[r], aLi = g_aLi[r];
    float sr = h0r[b * RR + r];
    float si = h0i[b * RR + r];
    for (int c = 0; c < CCH; c++) {
        int idx = (b * CCH + c) * RR + r;
        g_Sr[idx] = sr;
        g_Si[idx] = si;
        float pr = g_Pr[idx], pi = g_Pi[idx];
        float nsr = fmaf(aLr, sr, fmaf(-aLi, si, pr));
        float nsi = fmaf(aLr, si, fmaf(aLi, sr, pi));
        sr = nsr; si = nsi;
    }
    if (out_size >= MM * N2R + 2 * BB * RR) {
        out[MM * N2R + b * RR + r]            = sr;   // final_r
        out[MM * N2R + BB * RR + b * RR + r]  = si;   // final_i
    }
}

// ---------------------------------------------------------------------------
// Scan phase 3 + residual add + LayerNorm (fused).
// Block = 512 threads = all r channels of one (b, chunk). At each t the block
// holds the full 1024-wide y row (y1 = h_r + res, y2 = h_i + res) -> block
// reduce mean/var, write normalized output in place over the residual.
// ---------------------------------------------------------------------------
__global__ void __launch_bounds__(512) scan3_k(float* __restrict__ out,
                                               const float* __restrict__ gamma,
                                               const float* __restrict__ beta) {
    const int r = threadIdx.x;
    const int c = blockIdx.x;
    const int b = blockIdx.y;
    const int warp = r >> 5, lane = r & 31;

    __shared__ float sS[16], sQ[16], sMV[2];

    const float ar = g_ar[r], ai = g_ai[r];
    int idx = (b * CCH + c) * RR + r;
    float hr = g_Sr[idx], hi = g_Si[idx];
    const float g1 = gamma[r], g2 = gamma[RR + r];
    const float be1 = beta[r], be2 = beta[RR + r];

    const float* xp = g_x + ((size_t)(b * TT + c * LCH)) * RR + r;
    float* op = out + ((size_t)(b * TT + c * LCH)) * N2R;

    for (int j = 0; j < LCH; j++) {
        float x = xp[(size_t)j * RR];
        float nhr = fmaf(ar, hr, fmaf(-ai, hi, x));
        float nhi = fmaf(ar, hi, ai * hr);
        hr = nhr; hi = nhi;

        float y1 = hr + op[(size_t)j * N2R + r];
        float y2 = hi + op[(size_t)j * N2R + RR + r];

        float s = y1 + y2;
        float q = fmaf(y1, y1, y2 * y2);
        #pragma unroll
        for (int o = 16; o; o >>= 1) {
            s += __shfl_xor_sync(0xffffffffu, s, o);
            q += __shfl_xor_sync(0xffffffffu, q, o);
        }
        if (lane == 0) { sS[warp] = s; sQ[warp] = q; }
        __syncthreads();
        if (warp == 0) {
            float s2 = (lane < 16) ? sS[lane] : 0.0f;
            float q2 = (lane < 16) ? sQ[lane] : 0.0f;
            #pragma unroll
            for (int o = 8; o; o >>= 1) {
                s2 += __shfl_xor_sync(0xffffffffu, s2, o);
                q2 += __shfl_xor_sync(0xffffffffu, q2, o);
            }
            if (lane == 0) {
                float mean = s2 * (1.0f / 1024.0f);
                float var  = fmaf(-mean, mean, q2 * (1.0f / 1024.0f));
                sMV[0] = mean;
                sMV[1] = rsqrtf(var + 1e-5f);
            }
        }
        __syncthreads();
        float mean = sMV[0], rstd = sMV[1];
        op[(size_t)j * N2R + r]      = fmaf((y1 - mean) * rstd, g1, be1);
        op[(size_t)j * N2R + RR + r] = fmaf((y2 - mean) * rstd, g2, be2);
    }
}

// ---------------------------------------------------------------------------
extern "C" void kernel_launch(void* const* d_in, const int* in_sizes, int n_in,
                              void* d_out, int out_size) {
    const float* u     = (const float*)d_in[0];
    const float* h0r   = (const float*)d_in[1];
    const float* h0i   = (const float*)d_in[2];
    const float* lraw  = (const float*)d_in[3];
    const float* omega = (const float*)d_in[4];
    const float* Wp    = (const float*)d_in[5];
    const float* Wr    = (const float*)d_in[6];
    const float* gamma = (const float*)d_in[7];
    const float* beta  = (const float*)d_in[8];
    float* out = (float*)d_out;

    setup_k<<<1, RR>>>(lraw, omega);
    gemm_k<<<dim3(NN / BN, MM / BM), 256>>>(u, Wp, Wr, out);
    scan1_k<<<dim3(CCH, BB), 512>>>();
    scan2_k<<<BB, 512>>>(h0r, h0i, out, out_size);
    scan3_k<<<dim3(CCH, BB), 512>>>(out, gamma, beta);
}

// round 3
// speedup vs baseline: 4.0682x; 4.0682x over previous
#include <cuda_runtime.h>
#include <cuda_bf16.h>
#include <stdint.h>
#include <math.h>

// Problem constants
#define BB 8
#define TT 4096
#define DD 1024
#define RR 512
#define N2R 1024
#define MM (BB*TT)        // 32768
#define NN 1536           // R + 2R
#define KK 1024
#define LCH 64
#define CCH 64

// Scratch
__device__ float g_x [MM * RR];            // 64 MB : u @ W_proj^T
__device__ float g_ar[RR], g_ai[RR];
__device__ float g_aLr[RR], g_aLi[RR];
__device__ float g_Pr[BB*CCH*RR], g_Pi[BB*CCH*RR];
__device__ float g_Sr[BB*CCH*RR], g_Si[BB*CCH*RR];
__device__ __nv_bfloat16 g_uh[MM*KK], g_ul[MM*KK];   // split u
__device__ __nv_bfloat16 g_wh[NN*KK], g_wl[NN*KK];   // split [Wp;Wr]

// ---------------------------------------------------------------------------
// Helpers
// ---------------------------------------------------------------------------
__device__ __forceinline__ uint32_t smem_u32(const void* p) {
    uint32_t a;
    asm("{ .reg .u64 t; cvta.to.shared.u64 t, %1; cvt.u32.u64 %0, t; }" : "=r"(a) : "l"(p));
    return a;
}
#define CP_ASYNC16(d, s)  asm volatile("cp.async.cg.shared.global [%0], [%1], 16;" :: "r"(d), "l"(s) : "memory")
#define CP_COMMIT()       asm volatile("cp.async.commit_group;" ::: "memory")
#define CP_WAIT1()        asm volatile("cp.async.wait_group 1;" ::: "memory")
#define CP_WAIT0()        asm volatile("cp.async.wait_group 0;" ::: "memory")

#define LDSM_X4(r0,r1,r2,r3, addr) \
    asm volatile("ldmatrix.sync.aligned.m8n8.x4.shared.b16 {%0,%1,%2,%3}, [%4];" \
        : "=r"(r0), "=r"(r1), "=r"(r2), "=r"(r3) : "r"(addr))

#define MMA16816(c, a0,a1,a2,a3, b0,b1) \
    asm volatile("mma.sync.aligned.m16n8k16.row.col.f32.bf16.bf16.f32 " \
        "{%0,%1,%2,%3}, {%4,%5,%6,%7}, {%8,%9}, {%0,%1,%2,%3};" \
        : "+f"((c)[0]), "+f"((c)[1]), "+f"((c)[2]), "+f"((c)[3]) \
        : "r"(a0), "r"(a1), "r"(a2), "r"(a3), "r"(b0), "r"(b1))

// ---------------------------------------------------------------------------
// Setup: recurrence coefficients
// ---------------------------------------------------------------------------
__global__ void setup_k(const float* __restrict__ lambda_raw,
                        const float* __restrict__ omega) {
    int r = threadIdx.x;
    float lr  = lambda_raw[r];
    float sig = 1.0f / (1.0f + expf(-lr));
    float lam = -5.0f * sig;
    float mag = expf(lam);
    float w   = omega[r];
    float sw, cw; sincosf(w, &sw, &cw);
    g_ar[r] = mag * cw;
    g_ai[r] = mag * sw;
    float magL = expf(lam * (float)LCH);
    float sl, cl; sincosf(w * (float)LCH, &sl, &cl);
    g_aLr[r] = magL * cl;
    g_aLi[r] = magL * sl;
}

// ---------------------------------------------------------------------------
// Split conversions fp32 -> (hi, lo) bf16
// ---------------------------------------------------------------------------
__global__ void __launch_bounds__(256) convu_k(const float* __restrict__ u) {
    int i = blockIdx.x * 256 + threadIdx.x;          // float4 index
    float4 v = ((const float4*)u)[i];
    __nv_bfloat16 h0 = __float2bfloat16_rn(v.x);
    __nv_bfloat16 h1 = __float2bfloat16_rn(v.y);
    __nv_bfloat16 h2 = __float2bfloat16_rn(v.z);
    __nv_bfloat16 h3 = __float2bfloat16_rn(v.w);
    __nv_bfloat16 l0 = __float2bfloat16_rn(v.x - __bfloat162float(h0));
    __nv_bfloat16 l1 = __float2bfloat16_rn(v.y - __bfloat162float(h1));
    __nv_bfloat16 l2 = __float2bfloat16_rn(v.z - __bfloat162float(h2));
    __nv_bfloat16 l3 = __float2bfloat16_rn(v.w - __bfloat162float(h3));
    ((__nv_bfloat162*)g_uh)[i*2]   = __nv_bfloat162(h0, h1);
    ((__nv_bfloat162*)g_uh)[i*2+1] = __nv_bfloat162(h2, h3);
    ((__nv_bfloat162*)g_ul)[i*2]   = __nv_bfloat162(l0, l1);
    ((__nv_bfloat162*)g_ul)[i*2+1] = __nv_bfloat162(l2, l3);
}

__global__ void __launch_bounds__(256) convw_k(const float* __restrict__ Wp,
                                               const float* __restrict__ Wr) {
    int i = blockIdx.x * 256 + threadIdx.x;
    int elem = i * 4;
    int row = elem >> 10, col = elem & 1023;
    const float* src = (row < RR) ? (Wp + (size_t)row * KK + col)
                                  : (Wr + (size_t)(row - RR) * KK + col);
    float4 v = *(const float4*)src;
    __nv_bfloat16 h0 = __float2bfloat16_rn(v.x);
    __nv_bfloat16 h1 = __float2bfloat16_rn(v.y);
    __nv_bfloat16 h2 = __float2bfloat16_rn(v.z);
    __nv_bfloat16 h3 = __float2bfloat16_rn(v.w);
    __nv_bfloat16 l0 = __float2bfloat16_rn(v.x - __bfloat162float(h0));
    __nv_bfloat16 l1 = __float2bfloat16_rn(v.y - __bfloat162float(h1));
    __nv_bfloat16 l2 = __float2bfloat16_rn(v.z - __bfloat162float(h2));
    __nv_bfloat16 l3 = __float2bfloat16_rn(v.w - __bfloat162float(h3));
    ((__nv_bfloat162*)g_wh)[i*2]   = __nv_bfloat162(h0, h1);
    ((__nv_bfloat162*)g_wh)[i*2+1] = __nv_bfloat162(h2, h3);
    ((__nv_bfloat162*)g_wl)[i*2]   = __nv_bfloat162(l0, l1);
    ((__nv_bfloat162*)g_wl)[i*2+1] = __nv_bfloat162(l2, l3);
}

// ---------------------------------------------------------------------------
// HMMA (mma.sync bf16) GEMM with 3-term split:
//   C = Ah*Bh + Ah*Bl + Al*Bh  (fp32 accum)
// 128x128 tile, BK=32, 2-stage cp.async double buffer, 8 warps (4m x 2n),
// warp tile 32x64. Smem tiles padded to 80B row stride (conflict-free ldsm).
// ---------------------------------------------------------------------------
#define BK 32
#define NK (KK/BK)          // 32
#define ROWB 80             // padded row stride in bytes (32 bf16 = 64B + 16B pad)
#define TILE_B (128*ROWB)   // 10240 per operand tile
#define STAGE_B (4*TILE_B)  // 40960
#define SMEM_GEMM (2*STAGE_B)  // 81920

__global__ void __launch_bounds__(256, 2)
gemm_k(float* __restrict__ outRes) {
    extern __shared__ char smem[];
    const uint32_t sb = smem_u32(smem);
    const int tid = threadIdx.x;
    const int wid = tid >> 5, lane = tid & 31;
    const int warp_m = wid & 3;          // 0..3  -> m offset *32
    const int warp_n = wid >> 2;         // 0..1  -> n offset *64
    const int bx = blockIdx.x, by = blockIdx.y;

    const char* gsrc[4];
    gsrc[0] = (const char*)(g_uh + (size_t)(by * 128) * KK);
    gsrc[1] = (const char*)(g_ul + (size_t)(by * 128) * KK);
    gsrc[2] = (const char*)(g_wh + (size_t)(bx * 128) * KK);
    gsrc[3] = (const char*)(g_wl + (size_t)(bx * 128) * KK);

    // cp.async: 4 tiles * 128 rows * 4 chunks(16B) = 2048 chunks; 8 per thread
    auto load_chunk = [&](int kt, int s) {
        uint32_t stage = sb + (uint32_t)s * STAGE_B;
        #pragma unroll
        for (int op = 0; op < 4; op++) {
            uint32_t t0 = stage + (uint32_t)op * TILE_B;
            const char* g = gsrc[op] + (size_t)kt * (BK * 2);
            #pragma unroll
            for (int i = 0; i < 2; i++) {
                int q = i * 256 + tid;           // 0..511
                int r = q >> 2, c = q & 3;
                CP_ASYNC16(t0 + (uint32_t)r * ROWB + c * 16,
                           g + (size_t)r * (KK * 2) + c * 16);
            }
        }
    };

    // ldmatrix lane-derived offsets
    //   A: row = warp_m*32 + (lane&15) (+ mt*16), kbyte = ((lane>>4)<<4) (+ kk*32)
    //   B: n   = warp_n*64 + p*16 + ((lane>>4)<<3) + (lane&7), kbyte = ((lane>>3)&1)<<4
    const uint32_t a_off = (uint32_t)(warp_m * 32 + (lane & 15)) * ROWB + ((lane >> 4) << 4);
    const uint32_t b_off = (uint32_t)(warp_n * 64 + ((lane >> 4) << 3) + (lane & 7)) * ROWB
                         + (((lane >> 3) & 1) << 4);

    float acc[2][8][4];
    #pragma unroll
    for (int mt = 0; mt < 2; mt++)
        #pragma unroll
        for (int nt = 0; nt < 8; nt++)
            #pragma unroll
            for (int e = 0; e < 4; e++) acc[mt][nt][e] = 0.0f;

    load_chunk(0, 0); CP_COMMIT();
    load_chunk(1, 1); CP_COMMIT();

    for (int kt = 0; kt < NK; kt++) {
        const int s = kt & 1;
        if (kt >= NK - 2) { CP_WAIT0(); } else { CP_WAIT1(); }
        __syncthreads();

        uint32_t stage = sb + (uint32_t)s * STAGE_B;
        uint32_t sAh = stage + a_off;
        uint32_t sAl = stage + TILE_B + a_off;
        uint32_t sBh = stage + 2 * TILE_B + b_off;
        uint32_t sBl = stage + 3 * TILE_B + b_off;

        #pragma unroll
        for (int kk = 0; kk < 2; kk++) {
            const uint32_t ko = kk * 32;
            uint32_t ah[2][4], al[2][4];
            #pragma unroll
            for (int mt = 0; mt < 2; mt++) {
                LDSM_X4(ah[mt][0], ah[mt][1], ah[mt][2], ah[mt][3], sAh + mt * (16 * ROWB) + ko);
                LDSM_X4(al[mt][0], al[mt][1], al[mt][2], al[mt][3], sAl + mt * (16 * ROWB) + ko);
            }
            #pragma unroll
            for (int p = 0; p < 4; p++) {
                uint32_t bh0, bh1, bh2, bh3, bl0, bl1, bl2, bl3;
                LDSM_X4(bh0, bh1, bh2, bh3, sBh + p * (16 * ROWB) + ko);
                LDSM_X4(bl0, bl1, bl2, bl3, sBl + p * (16 * ROWB) + ko);
                #pragma unroll
                for (int mt = 0; mt < 2; mt++) {
                    MMA16816(acc[mt][p*2],   ah[mt][0], ah[mt][1], ah[mt][2], ah[mt][3], bh0, bh1);
                    MMA16816(acc[mt][p*2+1], ah[mt][0], ah[mt][1], ah[mt][2], ah[mt][3], bh2, bh3);
                    MMA16816(acc[mt][p*2],   ah[mt][0], ah[mt][1], ah[mt][2], ah[mt][3], bl0, bl1);
                    MMA16816(acc[mt][p*2+1], ah[mt][0], ah[mt][1], ah[mt][2], ah[mt][3], bl2, bl3);
                    MMA16816(acc[mt][p*2],   al[mt][0], al[mt][1], al[mt][2], al[mt][3], bh0, bh1);
                    MMA16816(acc[mt][p*2+1], al[mt][0], al[mt][1], al[mt][2], al[mt][3], bh2, bh3);
                }
            }
        }
        __syncthreads();
        if (kt + 2 < NK) { load_chunk(kt + 2, s); CP_COMMIT(); }
    }

    // Epilogue: C fragment (m16n8): c0,c1 @ (t/4, 2*(t%4)); c2,c3 @ (t/4+8, ...)
    float* Cb; int ld;
    if (bx < 4) { Cb = g_x    + (size_t)(by * 128) * RR  + bx * 128;        ld = RR;  }
    else        { Cb = outRes + (size_t)(by * 128) * N2R + (bx * 128 - 512); ld = N2R; }
    const int r0 = warp_m * 32 + (lane >> 2);
    const int c0 = warp_n * 64 + 2 * (lane & 3);
    #pragma unroll
    for (int mt = 0; mt < 2; mt++) {
        #pragma unroll
        for (int nt = 0; nt < 8; nt++) {
            float* p0 = Cb + (size_t)(r0 + mt * 16)     * ld + c0 + nt * 8;
            float* p1 = Cb + (size_t)(r0 + mt * 16 + 8) * ld + c0 + nt * 8;
            *(float2*)p0 = make_float2(acc[mt][nt][0], acc[mt][nt][1]);
            *(float2*)p1 = make_float2(acc[mt][nt][2], acc[mt][nt][3]);
        }
    }
}

// ---------------------------------------------------------------------------
// Scan phase 1: chunk-local recurrences
// ---------------------------------------------------------------------------
__global__ void __launch_bounds__(512) scan1_k() {
    const int r = threadIdx.x;
    const int c = blockIdx.x;
    const int b = blockIdx.y;
    const float ar = g_ar[r], ai = g_ai[r];
    const float* xp = g_x + ((size_t)(b * TT + c * LCH)) * RR + r;
    float hr = 0.0f, hi = 0.0f;
    #pragma unroll 4
    for (int j = 0; j < LCH; j++) {
        float x = xp[(size_t)j * RR];
        float nhr = fmaf(ar, hr, fmaf(-ai, hi, x));
        float nhi = fmaf(ar, hi, ai * hr);
        hr = nhr; hi = nhi;
    }
    int idx = (b * CCH + c) * RR + r;
    g_Pr[idx] = hr;
    g_Pi[idx] = hi;
}

// ---------------------------------------------------------------------------
// Scan phase 2: cross-chunk combine + final state outputs
// ---------------------------------------------------------------------------
__global__ void __launch_bounds__(512) scan2_k(const float* __restrict__ h0r,
                                               const float* __restrict__ h0i,
                                               float* __restrict__ out,
                                               int out_size) {
    const int r = threadIdx.x;
    const int b = blockIdx.x;
    const float aLr = g_aLr[r], aLi = g_aLi[r];
    float sr = h0r[b * RR + r];
    float si = h0i[b * RR + r];
    int idx0 = b * CCH * RR + r;
    float pr_n = g_Pr[idx0], pi_n = g_Pi[idx0];
    #pragma unroll 8
    for (int c = 0; c < CCH; c++) {
        int idx = idx0 + c * RR;
        float pr = pr_n, pi = pi_n;
        if (c + 1 < CCH) { pr_n = g_Pr[idx + RR]; pi_n = g_Pi[idx + RR]; }
        g_Sr[idx] = sr;
        g_Si[idx] = si;
        float nsr = fmaf(aLr, sr, fmaf(-aLi, si, pr));
        float nsi = fmaf(aLr, si, fmaf(aLi, sr, pi));
        sr = nsr; si = nsi;
    }
    if (out_size >= MM * N2R + 2 * BB * RR) {
        out[MM * N2R + b * RR + r]           = sr;
        out[MM * N2R + BB * RR + b * RR + r] = si;
    }
}

// ---------------------------------------------------------------------------
// Scan phase 3 + residual + LayerNorm (fused)
// ---------------------------------------------------------------------------
__global__ void __launch_bounds__(512) scan3_k(float* __restrict__ out,
                                               const float* __restrict__ gamma,
                                               const float* __restrict__ beta) {
    const int r = threadIdx.x;
    const int c = blockIdx.x;
    const int b = blockIdx.y;
    const int warp = r >> 5, lane = r & 31;

    __shared__ float sS[16], sQ[16], sMV[2];

    const float ar = g_ar[r], ai = g_ai[r];
    int idx = (b * CCH + c) * RR + r;
    float hr = g_Sr[idx], hi = g_Si[idx];
    const float g1 = gamma[r], g2 = gamma[RR + r];
    const float be1 = beta[r], be2 = beta[RR + r];

    const float* xp = g_x + ((size_t)(b * TT + c * LCH)) * RR + r;
    float* op = out + ((size_t)(b * TT + c * LCH)) * N2R;

    for (int j = 0; j < LCH; j++) {
        float x = xp[(size_t)j * RR];
        float nhr = fmaf(ar, hr, fmaf(-ai, hi, x));
        float nhi = fmaf(ar, hi, ai * hr);
        hr = nhr; hi = nhi;

        float y1 = hr + op[(size_t)j * N2R + r];
        float y2 = hi + op[(size_t)j * N2R + RR + r];

        float s = y1 + y2;
        float q = fmaf(y1, y1, y2 * y2);
        #pragma unroll
        for (int o = 16; o; o >>= 1) {
            s += __shfl_xor_sync(0xffffffffu, s, o);
            q += __shfl_xor_sync(0xffffffffu, q, o);
        }
        if (lane == 0) { sS[warp] = s; sQ[warp] = q; }
        __syncthreads();
        if (warp == 0) {
            float s2 = (lane < 16) ? sS[lane] : 0.0f;
            float q2 = (lane < 16) ? sQ[lane] : 0.0f;
            #pragma unroll
            for (int o = 8; o; o >>= 1) {
                s2 += __shfl_xor_sync(0xffffffffu, s2, o);
                q2 += __shfl_xor_sync(0xffffffffu, q2, o);
            }
            if (lane == 0) {
                float mean = s2 * (1.0f / 1024.0f);
                float var  = fmaf(-mean, mean, q2 * (1.0f / 1024.0f));
                sMV[0] = mean;
                sMV[1] = rsqrtf(var + 1e-5f);
            }
        }
        __syncthreads();
        float mean = sMV[0], rstd = sMV[1];
        op[(size_t)j * N2R + r]      = fmaf((y1 - mean) * rstd, g1, be1);
        op[(size_t)j * N2R + RR + r] = fmaf((y2 - mean) * rstd, g2, be2);
    }
}

// ---------------------------------------------------------------------------
extern "C" void kernel_launch(void* const* d_in, const int* in_sizes, int n_in,
                              void* d_out, int out_size) {
    const float* u     = (const float*)d_in[0];
    const float* h0r   = (const float*)d_in[1];
    const float* h0i   = (const float*)d_in[2];
    const float* lraw  = (const float*)d_in[3];
    const float* omega = (const float*)d_in[4];
    const float* Wp    = (const float*)d_in[5];
    const float* Wr    = (const float*)d_in[6];
    const float* gamma = (const float*)d_in[7];
    const float* beta  = (const float*)d_in[8];
    float* out = (float*)d_out;

    cudaFuncSetAttribute(gemm_k, cudaFuncAttributeMaxDynamicSharedMemorySize, SMEM_GEMM);

    setup_k<<<1, RR>>>(lraw, omega);
    convw_k<<<NN * KK / 4 / 256, 256>>>(Wp, Wr);
    convu_k<<<MM * KK / 4 / 256, 256>>>(u);
    gemm_k<<<dim3(NN / 128, MM / 128), 256, SMEM_GEMM>>>(out);
    scan1_k<<<dim3(CCH, BB), 512>>>();
    scan2_k<<<BB, 512>>>(h0r, h0i, out, out_size);
    scan3_k<<<dim3(CCH, BB), 512>>>(out, gamma, beta);
}